// round 3
// baseline (speedup 1.0000x reference)
#include <cuda_runtime.h>

#define CCH 512
#define HH 192
#define WW 192
#define LL 36864
#define KK 64
#define EPSF 1e-12f

typedef unsigned long long u64;

// ---------------- static scratch (no allocations allowed) ----------------
__device__ float g_invn[LL];
__device__ float g_soft[KK*LL];
__device__ u64   g_mask[LL];
__device__ float g_sa2[KK*LL];   // weight (no invn folded)
__device__ float g_S[KK];
__device__ float g_vlad[KK*CCH];
__device__ float g_gsq;

// ---------------- K0: zero accumulators ----------------
__global__ void k_zero(){
    int i = blockIdx.x*256 + threadIdx.x;
    if (i < KK*CCH) g_vlad[i] = 0.f;
    if (i == 0) g_gsq = 0.f;
}

// ---------------- K1: per-pixel 1/||x[:,l]|| ----------------
__global__ __launch_bounds__(256) void k_invn(const float* __restrict__ x){
    int l = blockIdx.x*256 + threadIdx.x;
    float s = 0.f;
    #pragma unroll 8
    for (int c = 0; c < CCH; c++){
        float v = x[c*LL + l];
        s += v*v;
    }
    g_invn[l] = 1.f / fmaxf(sqrtf(s), EPSF);
}

// ---------------- K2: GEMM1 + invn scale + softmax + top2 mask ----------------
// Block: 256 threads, 64 k x 128 pixels. C-chunks of 8.
__global__ __launch_bounds__(256) void k_logits(const float* __restrict__ x,
                                                const float* __restrict__ cw){
    __shared__ float lsm[KK*128];               // 32KB; tiles aliased at front
    __shared__ float invs[128], mxs[128], rss[128];
    float* Ws = lsm;            // [64][8]
    float* Xs = lsm + 512;      // [8][128]

    const int tid  = threadIdx.x;
    const int pix0 = blockIdx.x * 128;
    const int tl   = tid & 31;     // pixel lane: l = tl + 32*ll
    const int tkq  = tid >> 5;     // k group: k = tkq*8 + kk (warp-uniform -> broadcast LDS)

    float acc[8][4];
    #pragma unroll
    for (int a = 0; a < 8; a++)
        #pragma unroll
        for (int b = 0; b < 4; b++) acc[a][b] = 0.f;

    if (tid < 128) invs[tid] = g_invn[pix0 + tid];

    for (int c0 = 0; c0 < CCH; c0 += 8){
        __syncthreads();
        #pragma unroll
        for (int i = tid; i < 512; i += 256)
            Ws[i] = cw[(i>>3)*CCH + c0 + (i&7)];
        #pragma unroll
        for (int i = tid; i < 1024; i += 256)
            Xs[i] = x[(c0 + (i>>7))*LL + pix0 + (i&127)];
        __syncthreads();
        #pragma unroll
        for (int q = 0; q < 8; q++){
            float xv[4];
            #pragma unroll
            for (int ll = 0; ll < 4; ll++) xv[ll] = Xs[q*128 + tl + 32*ll];
            #pragma unroll
            for (int kk = 0; kk < 8; kk++){
                float w = Ws[(tkq*8+kk)*8 + q];
                #pragma unroll
                for (int ll = 0; ll < 4; ll++) acc[kk][ll] += w * xv[ll];
            }
        }
    }
    __syncthreads();

    // store invn-scaled logits to smem
    #pragma unroll
    for (int kk = 0; kk < 8; kk++)
        #pragma unroll
        for (int ll = 0; ll < 4; ll++){
            int l = tl + 32*ll;
            lsm[(tkq*8+kk)*128 + l] = acc[kk][ll] * invs[l];
        }
    __syncthreads();

    // per-pixel softmax stats + top-2 (threads 0..127)
    if (tid < 128){
        float v1 = -1e30f, v2 = -1e30f;
        int i1 = 0, i2 = 0;
        #pragma unroll
        for (int k = 0; k < KK; k++){
            float v = lsm[k*128 + tid];
            if (v > v1){ v2 = v1; i2 = i1; v1 = v; i1 = k; }
            else if (v > v2){ v2 = v; i2 = k; }
        }
        float mx = v1;
        float s = 0.f;
        #pragma unroll
        for (int k = 0; k < KK; k++) s += __expf(lsm[k*128 + tid] - mx);
        mxs[tid] = mx;
        rss[tid] = 1.f / s;
        g_mask[pix0 + tid] = (1ull << i1) | (1ull << i2);
    }
    __syncthreads();

    // write softmax probs to global
    for (int i = tid; i < KK*128; i += 256){
        int k = i >> 7, p = i & 127;
        g_soft[k*LL + pix0 + p] = __expf(lsm[i] - mxs[p]) * rss[p];
    }
}

// ---------------- K3: neighbor-count weight via CSA popcount ----------------
__device__ __forceinline__ void fa(u64 a, u64 b, u64 c, u64& s, u64& cy){
    u64 t = a ^ b; s = t ^ c; cy = (a & b) | (c & t);
}

__global__ __launch_bounds__(256) void k_weight(){
    int p = blockIdx.x*256 + threadIdx.x;
    int i = p / WW, j = p % WW;
    u64 m[9];
    int t = 0;
    #pragma unroll
    for (int di = -1; di <= 1; di++)
        #pragma unroll
        for (int dj = -1; dj <= 1; dj++){
            int ii = i + di, jj = j + dj;
            m[t++] = (ii >= 0 && ii < HH && jj >= 0 && jj < WW) ? g_mask[ii*WW + jj] : 0ull;
        }
    u64 s1,c1,s2,c2,s3,c3,s4,c4,s5,c5;
    fa(m[0],m[1],m[2],s1,c1);
    fa(m[3],m[4],m[5],s2,c2);
    fa(m[6],m[7],m[8],s3,c3);
    fa(s1,s2,s3,s4,c4);            // b0 = s4
    fa(c1,c2,c3,s5,c5);
    u64 b0 = s4;
    u64 b1 = s5 ^ c4;
    u64 u  = s5 & c4;
    u64 b2 = c5 ^ u;
    u64 b3 = c5 & u;

    int mi = min(i, HH-1-i), mj = min(j, WW-1-j);
    float mf = (float)min(mi, mj);
    float m2 = mf*mf;
    float poly = m2*m2;            // same op order as reference

    #pragma unroll 8
    for (int k = 0; k < KK; k++){
        int cnt = (int)((b0>>k)&1) + 2*(int)((b1>>k)&1)
                + 4*(int)((b2>>k)&1) + 8*(int)((b3>>k)&1);
        g_sa2[k*LL + p] = g_soft[k*LL + p] * (float)cnt * poly;
    }
}

// ---------------- K3b: S[k] = sum_l sa2[k,l] ----------------
__global__ __launch_bounds__(256) void k_ssum(){
    __shared__ float red[256];
    int k = blockIdx.x;
    float s = 0.f;
    for (int l = threadIdx.x; l < LL; l += 256) s += g_sa2[k*LL + l];
    red[threadIdx.x] = s;
    __syncthreads();
    for (int o = 128; o > 0; o >>= 1){
        if (threadIdx.x < o) red[threadIdx.x] += red[threadIdx.x + o];
        __syncthreads();
    }
    if (threadIdx.x == 0) g_S[k] = red[0];
}

// ---------------- K4: GEMM2 vlad[k,c] += sum_l sa2[k,l] * x[c,l]*invn[l] ----------------
// Tile 64k x 64c, L-chunk 256 per block, grid (144, 8).
__global__ __launch_bounds__(256) void k_vlad(const float* __restrict__ x){
    __shared__ float As[64*33];                       // sa2 [k][q], pad 33
    __shared__ __align__(16) float Bs[32*68];         // xn  [q][c], pad 68 (16B-aligned rows)
    const int tid = threadIdx.x;
    const int l0 = blockIdx.x * 256;
    const int c0 = blockIdx.y * 64;
    const int tc = tid & 15;       // c = c0 + tc*4 + cc
    const int tk = tid >> 4;       // k = tk + 16*kk

    float acc[4][4];
    #pragma unroll
    for (int a = 0; a < 4; a++)
        #pragma unroll
        for (int b = 0; b < 4; b++) acc[a][b] = 0.f;

    for (int ch = 0; ch < 8; ch++){
        int lb = l0 + ch*32;
        __syncthreads();
        #pragma unroll
        for (int i = tid; i < 2048; i += 256){
            int k = i >> 5, q = i & 31;
            As[k*33 + q] = g_sa2[k*LL + lb + q];
        }
        #pragma unroll
        for (int i = tid; i < 2048; i += 256){
            int cc = i >> 5, q = i & 31;
            Bs[q*68 + cc] = x[(c0+cc)*LL + lb + q] * g_invn[lb + q];
        }
        __syncthreads();
        #pragma unroll
        for (int q = 0; q < 32; q++){
            float4 bv = *(const float4*)&Bs[q*68 + tc*4];
            #pragma unroll
            for (int kk = 0; kk < 4; kk++){
                float a = As[(tk + 16*kk)*33 + q];
                acc[kk][0] += a * bv.x;
                acc[kk][1] += a * bv.y;
                acc[kk][2] += a * bv.z;
                acc[kk][3] += a * bv.w;
            }
        }
    }
    #pragma unroll
    for (int kk = 0; kk < 4; kk++){
        int k = tk + 16*kk;
        #pragma unroll
        for (int cc = 0; cc < 4; cc++)
            atomicAdd(&g_vlad[k*CCH + c0 + tc*4 + cc], acc[kk][cc]);
    }
}

// ---------------- K5: subtract centroid, row L2-normalize, accumulate global ssq ----------------
__global__ __launch_bounds__(256) void k_rownorm(const float* __restrict__ cent,
                                                 float* __restrict__ out){
    __shared__ float red[256];
    __shared__ float vsm[CCH];
    int k = blockIdx.x;
    float S = g_S[k];
    float s = 0.f;
    for (int c = threadIdx.x; c < CCH; c += 256){
        float v = g_vlad[k*CCH + c] - S * cent[k*CCH + c];
        vsm[c] = v;
        s += v*v;
    }
    red[threadIdx.x] = s;
    __syncthreads();
    for (int o = 128; o > 0; o >>= 1){
        if (threadIdx.x < o) red[threadIdx.x] += red[threadIdx.x + o];
        __syncthreads();
    }
    float rn = 1.f / fmaxf(sqrtf(red[0]), EPSF);
    for (int c = threadIdx.x; c < CCH; c += 256)
        out[k*CCH + c] = vsm[c] * rn;
    if (threadIdx.x == 0)
        atomicAdd(&g_gsq, red[0] * rn * rn);
}

// ---------------- K6: global L2 normalize ----------------
__global__ void k_gnorm(float* __restrict__ out){
    int i = blockIdx.x*256 + threadIdx.x;
    float r = 1.f / fmaxf(sqrtf(g_gsq), EPSF);
    out[i] *= r;
}

// ---------------- launch ----------------
extern "C" void kernel_launch(void* const* d_in, const int* in_sizes, int n_in,
                              void* d_out, int out_size){
    const float* x    = (const float*)d_in[0];   // [512, 192, 192]
    const float* cw   = (const float*)d_in[1];   // [64, 512]
    const float* cent = (const float*)d_in[2];   // [64, 512]
    float* out = (float*)d_out;                  // [64*512]
    (void)in_sizes; (void)n_in; (void)out_size;

    k_zero  <<<128, 256>>>();
    k_invn  <<<LL/256, 256>>>(x);
    k_logits<<<LL/128, 256>>>(x, cw);
    k_weight<<<LL/256, 256>>>();
    k_ssum  <<<KK, 256>>>();
    k_vlad  <<<dim3(144, 8), 256>>>(x);
    k_rownorm<<<KK, 256>>>(cent, out);
    k_gnorm <<<KK*CCH/256, 256>>>(out);
}

// round 4
// speedup vs baseline: 1.4756x; 1.4756x over previous
#include <cuda_runtime.h>

#define CCH 512
#define HH 192
#define WW 192
#define LL 36864
#define KK 64
#define EPSF 1e-12f

typedef unsigned long long u64;
typedef unsigned int u32;

// ---------------- static scratch (no allocations allowed) ----------------
__device__ float g_invn[LL];
__device__ float g_soft[KK*LL];
__device__ u64   g_mask[LL];
__device__ float g_sa2[KK*LL];
__device__ float g_S[KK];
__device__ float g_vlad[KK*CCH];
__device__ float g_gsq;

// ---------------- f32x2 helpers ----------------
__device__ __forceinline__ void ffma2(u64& d, u64 a, u64 b){
    asm("fma.rn.f32x2 %0, %1, %2, %0;" : "+l"(d) : "l"(a), "l"(b));
}
__device__ __forceinline__ u64 pack2(float a, float b){
    u64 r; asm("mov.b64 %0, {%1, %2};" : "=l"(r) : "f"(a), "f"(b)); return r;
}
__device__ __forceinline__ float lo2(u64 v){ return __uint_as_float((u32)v); }
__device__ __forceinline__ float hi2(u64 v){ return __uint_as_float((u32)(v >> 32)); }

// ---------------- K0: zero accumulators ----------------
__global__ void k_zero(){
    int i = blockIdx.x*256 + threadIdx.x;
    if (i < KK*CCH) g_vlad[i] = 0.f;
    if (i < KK)     g_S[i]    = 0.f;
    if (i == 0)     g_gsq     = 0.f;
}

// ---------------- K1: GEMM1 (f32x2) + invn + softmax + top2 mask ----------------
// Block: 256 threads, 64 k x 128 pixels. C in chunks of 8 (4 c-pairs).
__global__ __launch_bounds__(256) void k_logits(const float* __restrict__ x,
                                                const float* __restrict__ cw){
    __shared__ __align__(16) float lsm[KK*128];          // 32KB; tiles aliased at front
    __shared__ float invs[128], mxs[128], rss[128], ssqs[256];
    u64* Wsu  = (u64*)lsm;              // [64][4]  c-pairs (natural from conv_w)
    u64* Xspu = (u64*)lsm + 256;        // [4][130] pair-major: (cpair, pixel)

    const int tid  = threadIdx.x;
    const int pix0 = blockIdx.x * 128;
    const int tl   = tid & 31;          // pixel lane: l = tl + 32*ll
    const int tkq  = tid >> 5;          // k group:  k = tkq*8 + kk (warp-uniform)
    const int lp   = tid & 127;         // loader pixel
    const int lj   = tid >> 7;          // loader cpair base (0/1)

    u64 acc[8][4];
    #pragma unroll
    for (int a = 0; a < 8; a++)
        #pragma unroll
        for (int b = 0; b < 4; b++) acc[a][b] = 0ull;

    float ssq = 0.f;

    for (int c0 = 0; c0 < CCH; c0 += 8){
        __syncthreads();
        // W tile: 64 k x 4 c-pairs, direct u64 load (conv_w rows c-contiguous)
        Wsu[tid] = ((const u64*)cw)[(tid>>2)*(CCH/2) + (c0>>1) + (tid&3)];
        // X tile: 4 c-pairs x 128 pixels, pair-major
        #pragma unroll
        for (int s = 0; s < 2; s++){
            int jp = lj + 2*s;
            float v0 = x[(c0 + 2*jp    )*LL + pix0 + lp];
            float v1 = x[(c0 + 2*jp + 1)*LL + pix0 + lp];
            ssq += v0*v0 + v1*v1;
            Xspu[jp*130 + lp] = pack2(v0, v1);
        }
        __syncthreads();
        #pragma unroll
        for (int jp = 0; jp < 4; jp++){
            u64 xv[4];
            #pragma unroll
            for (int ll = 0; ll < 4; ll++) xv[ll] = Xspu[jp*130 + tl + 32*ll];
            #pragma unroll
            for (int kk = 0; kk < 8; kk++){
                u64 w = Wsu[(tkq*8 + kk)*4 + jp];
                #pragma unroll
                for (int ll = 0; ll < 4; ll++) ffma2(acc[kk][ll], w, xv[ll]);
            }
        }
    }

    // per-pixel 1/norm (each pixel's ssq split across threads t and t+128)
    __syncthreads();
    ssqs[tid] = ssq;
    __syncthreads();
    if (tid < 128){
        float s = ssqs[tid] + ssqs[tid + 128];
        float iv = 1.f / fmaxf(sqrtf(s), EPSF);
        invs[tid] = iv;
        g_invn[pix0 + tid] = iv;
    }
    __syncthreads();

    // scaled logits -> smem (overwrites tile staging area; all reads done)
    #pragma unroll
    for (int kk = 0; kk < 8; kk++)
        #pragma unroll
        for (int ll = 0; ll < 4; ll++){
            int l = tl + 32*ll;
            lsm[(tkq*8 + kk)*128 + l] = (lo2(acc[kk][ll]) + hi2(acc[kk][ll])) * invs[l];
        }
    __syncthreads();

    // per-pixel softmax stats + top-2 mask
    if (tid < 128){
        float v1 = -1e30f, v2 = -1e30f;
        int i1 = 0, i2 = 0;
        #pragma unroll
        for (int k = 0; k < KK; k++){
            float v = lsm[k*128 + tid];
            if (v > v1){ v2 = v1; i2 = i1; v1 = v; i1 = k; }
            else if (v > v2){ v2 = v; i2 = k; }
        }
        float s = 0.f;
        #pragma unroll
        for (int k = 0; k < KK; k++) s += __expf(lsm[k*128 + tid] - v1);
        mxs[tid] = v1;
        rss[tid] = 1.f / s;
        g_mask[pix0 + tid] = (1ull << i1) | (1ull << i2);
    }
    __syncthreads();

    for (int i = tid; i < KK*128; i += 256){
        int k = i >> 7, p = i & 127;
        g_soft[k*LL + pix0 + p] = __expf(lsm[i] - mxs[p]) * rss[p];
    }
}

// ---------------- K2: neighbor-count weight (CSA popcount) + fused S[k] ----------------
__device__ __forceinline__ void fa(u64 a, u64 b, u64 c, u64& s, u64& cy){
    u64 t = a ^ b; s = t ^ c; cy = (a & b) | (c & t);
}

__global__ __launch_bounds__(256) void k_weight(){
    const int p  = blockIdx.x*256 + threadIdx.x;
    const int k0 = blockIdx.y*16;
    __shared__ float ssm[16];
    if (threadIdx.x < 16) ssm[threadIdx.x] = 0.f;
    __syncthreads();

    const int i = p / WW, j = p % WW;
    u64 m[9];
    int t = 0;
    #pragma unroll
    for (int di = -1; di <= 1; di++)
        #pragma unroll
        for (int dj = -1; dj <= 1; dj++){
            int ii = i + di, jj = j + dj;
            m[t++] = (ii >= 0 && ii < HH && jj >= 0 && jj < WW) ? g_mask[ii*WW + jj] : 0ull;
        }
    u64 s1,c1,s2,c2,s3,c3,s4,c4,s5,c5;
    fa(m[0],m[1],m[2],s1,c1);
    fa(m[3],m[4],m[5],s2,c2);
    fa(m[6],m[7],m[8],s3,c3);
    fa(s1,s2,s3,s4,c4);
    fa(c1,c2,c3,s5,c5);
    u64 b0 = s4;
    u64 b1 = s5 ^ c4;
    u64 u  = s5 & c4;
    u64 b2 = c5 ^ u;
    u64 b3 = c5 & u;

    int mi = min(i, HH-1-i), mj = min(j, WW-1-j);
    float mf = (float)min(mi, mj);
    float m2 = mf*mf;
    float poly = m2*m2;

    #pragma unroll
    for (int kk = 0; kk < 16; kk++){
        int k = k0 + kk;
        int cnt = (int)((b0>>k)&1) + 2*(int)((b1>>k)&1)
                + 4*(int)((b2>>k)&1) + 8*(int)((b3>>k)&1);
        float v = g_soft[k*LL + p] * (float)cnt * poly;
        g_sa2[k*LL + p] = v;
        #pragma unroll
        for (int o = 16; o > 0; o >>= 1) v += __shfl_xor_sync(0xffffffffu, v, o);
        if ((threadIdx.x & 31) == 0) atomicAdd(&ssm[kk], v);
    }
    __syncthreads();
    if (threadIdx.x < 16) atomicAdd(&g_S[k0 + threadIdx.x], ssm[threadIdx.x]);
}

// ---------------- K3: GEMM2 (f32x2): vlad[k,c] += sum_l sa2[k,l]*x[c,l]*invn[l] ----------------
// Tile 64k x 64c, L-chunk 256 per block, grid (144, 8). l-pairs packed.
__global__ __launch_bounds__(256) void k_vlad(const float* __restrict__ x){
    __shared__ __align__(16) u64 Asu[64*17];   // sa2 pairs [k][qp], pitch 17
    __shared__ __align__(16) u64 Bsu[16*65];   // xn  pairs [qp][cc], pitch 65
    const int tid = threadIdx.x;
    const int l0  = blockIdx.x * 256;
    const int c0  = blockIdx.y * 64;
    const int tc  = tid & 15;      // c = c0 + tc + 16*cc
    const int tk  = tid >> 4;      // k = tk + 16*kk

    u64 acc[4][4];
    #pragma unroll
    for (int a = 0; a < 4; a++)
        #pragma unroll
        for (int b = 0; b < 4; b++) acc[a][b] = 0ull;

    for (int ch = 0; ch < 8; ch++){
        const int lb = l0 + ch*32;
        __syncthreads();
        #pragma unroll
        for (int jj = 0; jj < 4; jj++){
            int s = tid + jj*256;
            int k = s >> 4, qp = s & 15;
            Asu[k*17 + qp] = ((const u64*)(g_sa2 + k*LL + lb))[qp];
        }
        #pragma unroll
        for (int jj = 0; jj < 4; jj++){
            int s = tid + jj*256;
            int cc = s >> 4, qp = s & 15;
            u64 xv = ((const u64*)(x + (c0+cc)*LL + lb))[qp];
            u64 nv = ((const u64*)(g_invn + lb))[qp];
            Bsu[qp*65 + cc] = pack2(lo2(xv)*lo2(nv), hi2(xv)*hi2(nv));
        }
        __syncthreads();
        #pragma unroll
        for (int qp = 0; qp < 16; qp++){
            u64 bv[4];
            #pragma unroll
            for (int cc = 0; cc < 4; cc++) bv[cc] = Bsu[qp*65 + tc + 16*cc];
            #pragma unroll
            for (int kk = 0; kk < 4; kk++){
                u64 a = Asu[(tk + 16*kk)*17 + qp];
                #pragma unroll
                for (int cc = 0; cc < 4; cc++) ffma2(acc[kk][cc], a, bv[cc]);
            }
        }
    }
    #pragma unroll
    for (int kk = 0; kk < 4; kk++){
        int k = tk + 16*kk;
        #pragma unroll
        for (int cc = 0; cc < 4; cc++)
            atomicAdd(&g_vlad[k*CCH + c0 + tc + 16*cc],
                      lo2(acc[kk][cc]) + hi2(acc[kk][cc]));
    }
}

// ---------------- K4: centroid subtract + row L2 + global ssq ----------------
__global__ __launch_bounds__(256) void k_rownorm(const float* __restrict__ cent,
                                                 float* __restrict__ out){
    __shared__ float red[256];
    __shared__ float vsm[CCH];
    int k = blockIdx.x;
    float S = g_S[k];
    float s = 0.f;
    for (int c = threadIdx.x; c < CCH; c += 256){
        float v = g_vlad[k*CCH + c] - S * cent[k*CCH + c];
        vsm[c] = v;
        s += v*v;
    }
    red[threadIdx.x] = s;
    __syncthreads();
    for (int o = 128; o > 0; o >>= 1){
        if (threadIdx.x < o) red[threadIdx.x] += red[threadIdx.x + o];
        __syncthreads();
    }
    float rn = 1.f / fmaxf(sqrtf(red[0]), EPSF);
    for (int c = threadIdx.x; c < CCH; c += 256)
        out[k*CCH + c] = vsm[c] * rn;
    if (threadIdx.x == 0)
        atomicAdd(&g_gsq, red[0] * rn * rn);
}

// ---------------- K5: global L2 normalize ----------------
__global__ void k_gnorm(float* __restrict__ out){
    int i = blockIdx.x*256 + threadIdx.x;
    float r = 1.f / fmaxf(sqrtf(g_gsq), EPSF);
    out[i] *= r;
}

// ---------------- launch ----------------
extern "C" void kernel_launch(void* const* d_in, const int* in_sizes, int n_in,
                              void* d_out, int out_size){
    const float* x    = (const float*)d_in[0];   // [512, 192, 192]
    const float* cw   = (const float*)d_in[1];   // [64, 512]
    const float* cent = (const float*)d_in[2];   // [64, 512]
    float* out = (float*)d_out;                  // [64*512]
    (void)in_sizes; (void)n_in; (void)out_size;

    k_zero   <<<128, 256>>>();
    k_logits <<<LL/128, 256>>>(x, cw);
    k_weight <<<dim3(LL/256, 4), 256>>>();
    k_vlad   <<<dim3(144, 8), 256>>>(x);
    k_rownorm<<<KK, 256>>>(cent, out);
    k_gnorm  <<<KK*CCH/256, 256>>>(out);
}